// round 14
// baseline (speedup 1.0000x reference)
#include <cuda_runtime.h>
#include <cuda_fp16.h>
#include <cstdint>

#define NUM_E 1024
#define EDIM  256
#define NROWS 32768
#define SZQ   (6.0f / 127.0f)
#define QINV  (127.0f / 6.0f)
#define SC2   (2.0f * SZQ * SZQ)

// ---- device scratch ----
__device__ float g_cbnorm[NUM_E];                    // ||e_k||^2 exact
__device__ int g_pemax;                              // max_k sum|eq_k|
__device__ unsigned g_eemaxbits;                     // max_k clamp-excess sum (float bits)
__device__ signed char g_zq[NROWS * EDIM];           // [mtile*4+ch][128 row][64 B]
__device__ signed char g_eq[4 * NUM_E * 64];         // [ch][n][64 B]
__device__ __half g_dmat[(size_t)NROWS * NUM_E];     // approx distances fp16 (64MB)

// ---- screen smem layout ----
#define T_STRIDE 80                   // 64 B data + 16 pad (conflict-free ldmatrix)
#define TILE_BYTES 10240              // 128 rows * 80
#define B_BASE 20480
#define SMEM_TOTAL 40960              // 2 A bufs + 2 B bufs

__device__ __forceinline__ uint32_t smem_u32(const void* p) {
    uint32_t a;
    asm("{ .reg .u64 t; cvta.to.shared.u64 t, %1; cvt.u32.u64 %0, t; }" : "=r"(a) : "l"(p));
    return a;
}
__device__ __forceinline__ void cpasync16(uint32_t dst, const void* src) {
    asm volatile("cp.async.cg.shared.global [%0], [%1], 16;" :: "r"(dst), "l"(src));
}
__device__ __forceinline__ void ldsm_x4(uint32_t* r, uint32_t addr) {
    asm volatile("ldmatrix.sync.aligned.m8n8.x4.shared.b16 {%0,%1,%2,%3}, [%4];"
                 : "=r"(r[0]), "=r"(r[1]), "=r"(r[2]), "=r"(r[3]) : "r"(addr));
}
__device__ __forceinline__ void mma_s8(int* c, const uint32_t* a, uint32_t b0, uint32_t b1) {
    asm volatile("mma.sync.aligned.m16n8k32.row.col.s32.s8.s8.s32 "
                 "{%0,%1,%2,%3}, {%4,%5,%6,%7}, {%8,%9}, {%0,%1,%2,%3};"
                 : "+r"(c[0]), "+r"(c[1]), "+r"(c[2]), "+r"(c[3])
                 : "r"(a[0]), "r"(a[1]), "r"(a[2]), "r"(a[3]), "r"(b0), "r"(b1));
}
__device__ __forceinline__ unsigned ordf(float d) {
    unsigned u = __float_as_uint(d);
    return (u & 0x80000000u) ? ~u : (u | 0x80000000u);
}
__device__ __forceinline__ signed char q8(float v) {
    return (signed char)__float2int_rn(fminf(fmaxf(v, -6.0f), 6.0f) * QINV);
}

// ---------- prep: blocks [0,1024) codebook quantize+stats; [1024,2048) z transpose+quantize ----------
__global__ __launch_bounds__(256) void prep_kernel(const float* __restrict__ cb,
                                                   const float* __restrict__ z) {
    const int bid = blockIdx.x, t = threadIdx.x;
    if (bid < 1024) {
        int k = bid;
        float v = cb[(size_t)k * EDIM + t];
        signed char q = q8(v);
        g_eq[(size_t)(t >> 6) * (NUM_E * 64) + k * 64 + (t & 63)] = q;
        float sq = v * v;
        float aq = fabsf((float)q);
        float ex = fmaxf(fabsf(v) - 6.0f, 0.0f);
        #pragma unroll
        for (int o = 16; o; o >>= 1) {
            sq += __shfl_down_sync(0xffffffffu, sq, o);
            aq += __shfl_down_sync(0xffffffffu, aq, o);
            ex += __shfl_down_sync(0xffffffffu, ex, o);
        }
        __shared__ float ws[8], wa[8], we[8];
        if ((t & 31) == 0) { ws[t >> 5] = sq; wa[t >> 5] = aq; we[t >> 5] = ex; }
        __syncthreads();
        if (t == 0) {
            float s = 0.f, a = 0.f, e = 0.f;
            #pragma unroll
            for (int i = 0; i < 8; i++) { s += ws[i]; a += wa[i]; e += we[i]; }
            g_cbnorm[k] = s;
            atomicMax(&g_pemax, (int)(a + 0.5f));
            atomicMax(&g_eemaxbits, __float_as_uint(e));
        }
    } else {
        // z: block = (mtile, ch); read 64c x 128m, transpose, quantize
        const int zb = bid - 1024;
        const int mtile = zb >> 2, ch = zb & 3;
        const int m0 = mtile * 128, b = m0 >> 10, hw0 = m0 & 1023;
        __shared__ float s[64][129];
        #pragma unroll
        for (int i = 0; i < 8; i++) {
            int e = t + i * 256;                 // float4 id, 2048 total
            int crow = e >> 5, seg = e & 31;
            float4 f = *(const float4*)(z + (size_t)b * 262144
                        + (size_t)(ch * 64 + crow) * 1024 + hw0 + seg * 4);
            s[crow][seg * 4 + 0] = f.x; s[crow][seg * 4 + 1] = f.y;
            s[crow][seg * 4 + 2] = f.z; s[crow][seg * 4 + 3] = f.w;
        }
        __syncthreads();
        const int mr = t & 127, half = t >> 7;
        uint32_t pk[8];
        #pragma unroll
        for (int w4 = 0; w4 < 8; w4++) {
            uint32_t p = 0;
            #pragma unroll
            for (int j = 0; j < 4; j++) {
                signed char q = q8(s[half * 32 + w4 * 4 + j][mr]);
                p |= ((uint32_t)(unsigned char)q) << (j * 8);
            }
            pk[w4] = p;
        }
        signed char* dst = g_zq + ((size_t)(mtile * 4 + ch) * 128 + mr) * 64 + half * 32;
        ((uint4*)dst)[0] = *(uint4*)&pk[0];
        ((uint4*)dst)[1] = *(uint4*)&pk[4];
    }
}

// ---- async tile loaders (8 KB each: 128 rows x 64 B -> stride-80 smem) ----
__device__ __forceinline__ void issue_A(uint32_t dst, int mtile, int ch, int tid) {
    #pragma unroll
    for (int r = 0; r < 2; r++) {
        int e = tid + r * 256;
        int row = e >> 2, seg = e & 3;
        cpasync16(dst + row * T_STRIDE + seg * 16,
                  g_zq + (size_t)(mtile * 4 + ch) * 8192 + row * 64 + seg * 16);
    }
}
__device__ __forceinline__ void issue_B(uint32_t dst, int n0, int ch, int tid) {
    #pragma unroll
    for (int r = 0; r < 2; r++) {
        int e = tid + r * 256;
        int row = e >> 2, seg = e & 3;
        cpasync16(dst + row * T_STRIDE + seg * 16,
                  g_eq + (size_t)ch * 65536 + (size_t)(n0 + row) * 64 + seg * 16);
    }
}

// ---------- screen: int8 IMMA GEMM -> approx distance matrix (fp16) ----------
// grid = 2048 (256 mtiles x 8 ntiles), block = 256
__global__ __launch_bounds__(256, 2) void screen_kernel() {
    extern __shared__ __align__(16) unsigned char smem[];
    const uint32_t sb = smem_u32(smem);
    const int tid = threadIdx.x;
    const int lane = tid & 31;
    const int w = tid >> 5, wm = w & 1, wn = w >> 1;   // 2 m-warps x 4 n-warps
    const int ntile = blockIdx.x & 7, mtile = blockIdx.x >> 3;
    const int m0 = mtile * 128, n0 = ntile * 128;

    int acc[4][4][4];
    #pragma unroll
    for (int i = 0; i < 4; i++)
        #pragma unroll
        for (int j = 0; j < 4; j++)
            #pragma unroll
            for (int e = 0; e < 4; e++) acc[i][j][e] = 0;

    issue_A(sb, mtile, 0, tid);
    issue_B(sb + B_BASE, n0, 0, tid);
    asm volatile("cp.async.commit_group;");

    const uint32_t lrow = (lane & 15) * T_STRIDE + (lane >> 4) * 16;
    #pragma unroll 1
    for (int ch = 0; ch < 4; ch++) {
        const int buf = ch & 1;
        if (ch < 3) {
            const int nbuf = buf ^ 1;
            issue_A(sb + nbuf * TILE_BYTES, mtile, ch + 1, tid);
            issue_B(sb + B_BASE + nbuf * TILE_BYTES, n0, ch + 1, tid);
            asm volatile("cp.async.commit_group;");
            asm volatile("cp.async.wait_group 1;");
        } else {
            asm volatile("cp.async.wait_group 0;");
        }
        __syncthreads();

        const uint32_t asB = sb + buf * TILE_BYTES;
        const uint32_t bsB = sb + B_BASE + buf * TILE_BYTES;
        #pragma unroll
        for (int kk = 0; kk < 2; kk++) {
            uint32_t bb0[4], bb1[4];
            uint32_t baddr = bsB + (wn * 32) * T_STRIDE + lrow + kk * 32;
            ldsm_x4(bb0, baddr);
            ldsm_x4(bb1, baddr + 16 * T_STRIDE);
            #pragma unroll
            for (int i = 0; i < 4; i++) {
                uint32_t a[4];
                ldsm_x4(a, asB + (wm * 64 + i * 16) * T_STRIDE + lrow + kk * 32);
                mma_s8(acc[i][0], a, bb0[0], bb0[2]);
                mma_s8(acc[i][1], a, bb0[1], bb0[3]);
                mma_s8(acc[i][2], a, bb1[0], bb1[2]);
                mma_s8(acc[i][3], a, bb1[1], bb1[3]);
            }
        }
        __syncthreads();
    }

    // epilogue: d~ = ||e||^2 - 2*s^2*acc, store fp16
    const int g = lane >> 2, tg = lane & 3;
    float cbn[8];
    #pragma unroll
    for (int j = 0; j < 4; j++) {
        cbn[2 * j]     = __ldg(&g_cbnorm[n0 + wn * 32 + j * 8 + tg * 2]);
        cbn[2 * j + 1] = __ldg(&g_cbnorm[n0 + wn * 32 + j * 8 + tg * 2 + 1]);
    }
    #pragma unroll
    for (int i = 0; i < 4; i++) {
        #pragma unroll
        for (int h = 0; h < 2; h++) {
            int row = m0 + wm * 64 + i * 16 + h * 8 + g;
            #pragma unroll
            for (int j = 0; j < 4; j++) {
                float d0 = cbn[2 * j]     - SC2 * (float)acc[i][j][h * 2];
                float d1 = cbn[2 * j + 1] - SC2 * (float)acc[i][j][h * 2 + 1];
                int col = n0 + wn * 32 + j * 8 + tg * 2;
                __half2 v = __floats2half2_rn(d0, d1);
                *(uint32_t*)(g_dmat + (size_t)row * NUM_E + col) = *(uint32_t*)&v;
            }
        }
    }
}

// ---------- refine: scan + exact verify + fused outputs (warp/row, 8 rows/block) ----------
__global__ __launch_bounds__(256) void refine_kernel(const float* __restrict__ z,
                                                     const float* __restrict__ cb,
                                                     float* __restrict__ oh,
                                                     float* __restrict__ oq) {
    __shared__ float zrow[8][256];
    __shared__ int sidx[8];
    const int bid = blockIdx.x, tid = threadIdx.x;
    const int w = tid >> 5, lane = tid & 31;
    const int r0 = bid * 8, b = r0 >> 10, hw0 = r0 & 1023;
    for (int e = tid; e < 2048; e += 256) {
        int rr = e & 7, c = e >> 3;
        zrow[rr][c] = z[(size_t)b * 262144 + (size_t)c * 1024 + hw0 + rr];
    }
    __syncthreads();
    const int row = r0 + w;

    // row sums: sa = sum|z|, er = clamp excess
    float sa = 0.f, er = 0.f;
    #pragma unroll
    for (int i = 0; i < 8; i++) {
        float v = fabsf(zrow[w][lane + 32 * i]);
        sa += v;
        er += fmaxf(v - 6.0f, 0.0f);
    }
    #pragma unroll
    for (int o = 16; o; o >>= 1) {
        sa += __shfl_xor_sync(0xffffffffu, sa, o);
        er += __shfl_xor_sync(0xffffffffu, er, o);
    }

    // vectorized dmat scan (fp16): dv[iq*8+j] -> col (iq*32+lane)*8+j
    const uint4* d4 = (const uint4*)(g_dmat + (size_t)row * NUM_E) + lane;
    uint4 qv[4];
    #pragma unroll
    for (int i = 0; i < 4; i++) qv[i] = d4[i * 32];
    float dv[32];
    float dmin = 3.4e38f;
    #pragma unroll
    for (int i = 0; i < 4; i++) {
        const uint32_t* pp = (const uint32_t*)&qv[i];
        #pragma unroll
        for (int hj = 0; hj < 4; hj++) {
            float2 f = __half22float2(*(const __half2*)&pp[hj]);
            dv[i * 8 + hj * 2]     = f.x;
            dv[i * 8 + hj * 2 + 1] = f.y;
            dmin = fminf(dmin, fminf(f.x, f.y));
        }
    }
    #pragma unroll
    for (int o = 16; o; o >>= 1) dmin = fminf(dmin, __shfl_xor_sync(0xffffffffu, dmin, o));

    // rigorous window: per-entry error Q, accept d~ <= dmin + 2Q + margin
    float PR = sa / SZQ + 128.0f;
    float PE = (float)g_pemax;
    float EE = __uint_as_float(g_eemaxbits);
    float Bs = (SZQ * SZQ) * (0.5f * (PR + PE) + 64.0f) + 6.0f * er + (6.0f + er) * EE;
    float Q = 2.0f * Bs + 0.6f;                 // + fp16 rounding
    float T = dmin + 2.0f * Q + 4.0f;           // + margin

    unsigned cmask = 0;
    #pragma unroll
    for (int i = 0; i < 32; i++)
        if (dv[i] <= T) cmask |= (1u << i);

    unsigned long long best = ~0ull;
    unsigned active = __ballot_sync(0xffffffffu, cmask != 0);
    while (active) {
        int src = __ffs(active) - 1; active &= active - 1;
        unsigned bm = __shfl_sync(0xffffffffu, cmask, src);
        while (bm) {
            int i = __ffs(bm) - 1; bm &= bm - 1;
            int kc = ((i >> 3) * 32 + src) * 8 + (i & 7);
            const float* erow = cb + (size_t)kc * EDIM;
            float s = 0.f;
            #pragma unroll
            for (int jj = 0; jj < 8; jj++)
                s += zrow[w][lane + 32 * jj] * __ldg(&erow[lane + 32 * jj]);
            #pragma unroll
            for (int o = 16; o; o >>= 1) s += __shfl_xor_sync(0xffffffffu, s, o);
            float dist = __ldg(&g_cbnorm[kc]) - 2.0f * s;
            unsigned long long key = ((unsigned long long)ordf(dist) << 32) | (unsigned)kc;
            if (key < best) best = key;
        }
    }
    if (lane == 0) sidx[w] = (int)(best & 0xFFFFFFFFu);
    __syncthreads();

    // ---- fused outputs ----
    int idx[8];
    #pragma unroll
    for (int r = 0; r < 8; r++) idx[r] = sidx[r];

    #pragma unroll
    for (int r = 0; r < 8; r++) {
        int id = idx[r];
        float4 v = {0.f, 0.f, 0.f, 0.f};
        if ((id >> 2) == tid) {
            if ((id & 3) == 0) v.x = 1.f;
            else if ((id & 3) == 1) v.y = 1.f;
            else if ((id & 3) == 2) v.z = 1.f;
            else v.w = 1.f;
        }
        *(float4*)&oh[(size_t)(r0 + r) * NUM_E + tid * 4] = v;
    }

    float vals[8];
    #pragma unroll
    for (int r = 0; r < 8; r++)
        vals[r] = __ldg(&cb[(size_t)idx[r] * EDIM + tid]);
    float* qbase = oq + (size_t)b * 262144 + (size_t)tid * 1024 + hw0;
    *(float4*)qbase       = *(float4*)&vals[0];
    *(float4*)(qbase + 4) = *(float4*)&vals[4];
}

extern "C" void kernel_launch(void* const* d_in, const int* in_sizes, int n_in,
                              void* d_out, int out_size) {
    const float* z  = (const float*)d_in[0];
    const float* cb = (const float*)d_in[1];
    float* out_onehot = (float*)d_out;
    float* out_q      = (float*)d_out + (size_t)NROWS * NUM_E;

    cudaFuncSetAttribute(screen_kernel, cudaFuncAttributeMaxDynamicSharedMemorySize, SMEM_TOTAL);

    prep_kernel<<<2048, 256>>>(cb, z);
    screen_kernel<<<2048, 256, SMEM_TOTAL>>>();
    refine_kernel<<<NROWS / 8, 256>>>(z, cb, out_onehot, out_q);
}

// round 16
// speedup vs baseline: 2.2857x; 2.2857x over previous
#include <cuda_runtime.h>
#include <cuda_bf16.h>
#include <cstdint>

#define NUM_E 1024
#define EDIM  256
#define NROWS 32768

// ---- device scratch ----
__device__ float g_cbnorm[NUM_E];                  // ||e_k||^2
__device__ unsigned g_wmaxbits;                    // max ||e||^2 as float bits (nonneg)
__device__ __nv_bfloat16 g_b0[NUM_E * EDIM];       // bf16(codebook) [k][c]
__device__ __nv_bfloat16 g_z0[256 * 8 * 32 * 128]; // bf16(z) tiled [mtile][ch][cr][m]
__device__ __nv_bfloat16 g_dmat[(size_t)NROWS * NUM_E]; // approx distances (64MB)

// ---- smem layout for screen kernel (bytes) ----
#define AS_STRIDE 272                 // 128 m * 2B + 16 pad
#define AS_SUB    (32 * AS_STRIDE)    // 8704 (one 32-c sub-tile)
#define AS_BUF    (2 * AS_SUB)        // 17408 (64-c chunk)
#define BS_OFF    (2 * AS_BUF)        // 34816
#define BS_STRIDE 80
#define BS_SUB    (128 * BS_STRIDE)   // 10240 (one 32-c sub-tile)
#define BS_BUF    (2 * BS_SUB)        // 20480 (64-c chunk)
#define SMEM_TOTAL (BS_OFF + 2 * BS_BUF)  // 75776 -> 2 CTAs/SM

__device__ __forceinline__ uint32_t smem_u32(const void* p) {
    uint32_t a;
    asm("{ .reg .u64 t; cvta.to.shared.u64 t, %1; cvt.u32.u64 %0, t; }" : "=r"(a) : "l"(p));
    return a;
}
__device__ __forceinline__ void cpasync16(uint32_t dst, const void* src) {
    asm volatile("cp.async.cg.shared.global [%0], [%1], 16;" :: "r"(dst), "l"(src));
}
__device__ __forceinline__ void ldsm_x4(uint32_t* r, uint32_t addr) {
    asm volatile("ldmatrix.sync.aligned.m8n8.x4.shared.b16 {%0,%1,%2,%3}, [%4];"
                 : "=r"(r[0]), "=r"(r[1]), "=r"(r[2]), "=r"(r[3]) : "r"(addr));
}
__device__ __forceinline__ void ldsm_x4t(uint32_t* r, uint32_t addr) {
    asm volatile("ldmatrix.sync.aligned.m8n8.x4.trans.shared.b16 {%0,%1,%2,%3}, [%4];"
                 : "=r"(r[0]), "=r"(r[1]), "=r"(r[2]), "=r"(r[3]) : "r"(addr));
}
__device__ __forceinline__ void mma16816(float* c, const uint32_t* a, uint32_t b0, uint32_t b1) {
    asm volatile("mma.sync.aligned.m16n8k16.row.col.f32.bf16.bf16.f32 "
                 "{%0,%1,%2,%3}, {%4,%5,%6,%7}, {%8,%9}, {%0,%1,%2,%3};"
                 : "+f"(c[0]), "+f"(c[1]), "+f"(c[2]), "+f"(c[3])
                 : "r"(a[0]), "r"(a[1]), "r"(a[2]), "r"(a[3]), "r"(b0), "r"(b1));
}
__device__ __forceinline__ unsigned ordf(float d) {
    unsigned u = __float_as_uint(d);
    return (u & 0x80000000u) ? ~u : (u | 0x80000000u);
}

// ---------- merged prep: blocks [0,1024) codebook, [1024,3072) z ----------
__global__ __launch_bounds__(256) void prep_kernel(const float* __restrict__ cb,
                                                   const float* __restrict__ z) {
    const int bid = blockIdx.x, t = threadIdx.x;
    if (bid < 1024) {
        int k = bid;
        float v = cb[(size_t)k * EDIM + t];
        g_b0[(size_t)k * EDIM + t] = __float2bfloat16(v);
        float sq = v * v;
        #pragma unroll
        for (int o = 16; o; o >>= 1) sq += __shfl_down_sync(0xffffffffu, sq, o);
        __shared__ float ws[8];
        if ((t & 31) == 0) ws[t >> 5] = sq;
        __syncthreads();
        if (t == 0) {
            float s = 0.f;
            #pragma unroll
            for (int i = 0; i < 8; i++) s += ws[i];
            g_cbnorm[k] = s;
            atomicMax(&g_wmaxbits, __float_as_uint(s));
        }
    } else {
        const int zb = bid - 1024;               // zb = mtile*8 + ch
        const int mtile = zb >> 3, ch = zb & 7;
        const int cr = t >> 3, ms = (t & 7) * 16;
        const int m0 = mtile * 128;
        const float* src = z + ((size_t)(m0 >> 10) << 18) + (size_t)(ch * 32 + cr) * 1024 + (m0 & 1023) + ms;
        uint32_t o0[8];
        #pragma unroll
        for (int q = 0; q < 4; q++) {
            float4 f = ((const float4*)src)[q];
            __nv_bfloat162 v0 = __halves2bfloat162(__float2bfloat16(f.x), __float2bfloat16(f.y));
            __nv_bfloat162 v1 = __halves2bfloat162(__float2bfloat16(f.z), __float2bfloat16(f.w));
            o0[q * 2] = *(uint32_t*)&v0; o0[q * 2 + 1] = *(uint32_t*)&v1;
        }
        __nv_bfloat16* dst = g_z0 + ((size_t)zb * 32 + cr) * 128 + ms;
        ((uint4*)dst)[0] = *(uint4*)&o0[0];
        ((uint4*)dst)[1] = *(uint4*)&o0[4];
    }
}

// ---- async tile loaders (one 32-c sub-tile each) ----
__device__ __forceinline__ void issue_A(uint32_t dst, int mtile, int ch, int tid) {
    #pragma unroll
    for (int r = 0; r < 2; r++) {
        int e = tid + r * 256;
        int seg = e & 15, cr = e >> 4;
        cpasync16(dst + cr * AS_STRIDE + seg * 16,
                  g_z0 + ((size_t)(mtile * 8 + ch) * 32 + cr) * 128 + seg * 8);
    }
}
__device__ __forceinline__ void issue_B(uint32_t dst, int n0, int c0, int tid) {
    #pragma unroll
    for (int r = 0; r < 2; r++) {
        int e = tid + r * 256;
        int seg = e & 3, bn = e >> 2;
        cpasync16(dst + bn * BS_STRIDE + seg * 16,
                  g_b0 + (size_t)(n0 + bn) * EDIM + c0 + seg * 8);
    }
}

// ---------- screen: bf16 GEMM -> approx distance matrix (bf16) ----------
// grid = 2048 (256 mtiles x 8 ntiles), block = 256; K chunked 4 x 64
__global__ __launch_bounds__(256, 2) void screen_kernel() {
    extern __shared__ __align__(16) unsigned char smem[];
    const uint32_t sb = smem_u32(smem);
    const int tid = threadIdx.x;
    const int lane = tid & 31;
    const int w = tid >> 5, wm = w & 1, wn = w >> 1;   // 2 m-warps x 4 n-warps
    const int ntile = blockIdx.x & 7, mtile = blockIdx.x >> 3;
    const int m0 = mtile * 128, n0 = ntile * 128;

    float acc[4][4][4];
    #pragma unroll
    for (int i = 0; i < 4; i++)
        #pragma unroll
        for (int j = 0; j < 4; j++)
            #pragma unroll
            for (int e = 0; e < 4; e++) acc[i][j][e] = 0.f;

    // prologue: chunk 0 (two 32-c sub-tiles for A and B)
    issue_A(sb, mtile, 0, tid);
    issue_A(sb + AS_SUB, mtile, 1, tid);
    issue_B(sb + BS_OFF, n0, 0, tid);
    issue_B(sb + BS_OFF + BS_SUB, n0, 32, tid);
    asm volatile("cp.async.commit_group;");

    const int sel = lane >> 3, rr = lane & 7;
    #pragma unroll 1
    for (int ch = 0; ch < 4; ch++) {
        const int buf = ch & 1;
        if (ch < 3) {
            const int nbuf = buf ^ 1;
            issue_A(sb + nbuf * AS_BUF, mtile, (ch + 1) * 2, tid);
            issue_A(sb + nbuf * AS_BUF + AS_SUB, mtile, (ch + 1) * 2 + 1, tid);
            issue_B(sb + BS_OFF + nbuf * BS_BUF, n0, (ch + 1) * 64, tid);
            issue_B(sb + BS_OFF + nbuf * BS_BUF + BS_SUB, n0, (ch + 1) * 64 + 32, tid);
            asm volatile("cp.async.commit_group;");
            asm volatile("cp.async.wait_group 1;");
        } else {
            asm volatile("cp.async.wait_group 0;");
        }
        __syncthreads();

        const uint32_t asB = sb + buf * AS_BUF;
        const uint32_t bsB = sb + BS_OFF + buf * BS_BUF;
        #pragma unroll
        for (int ks = 0; ks < 4; ks++) {
            const int sub = ks >> 1;
            const int k0 = (ks & 1) * 16;
            uint32_t bb[8];
            uint32_t baddr = bsB + sub * BS_SUB
                           + (wn * 32 + (sel >> 1) * 8 + rr) * BS_STRIDE
                           + (k0 + (sel & 1) * 8) * 2;
            ldsm_x4(bb, baddr);
            ldsm_x4(bb + 4, baddr + 16 * BS_STRIDE);
            #pragma unroll
            for (int i = 0; i < 4; i++) {
                uint32_t a[4];
                uint32_t aaddr = asB + sub * AS_SUB
                               + (k0 + (sel >> 1) * 8 + rr) * AS_STRIDE
                               + (wm * 64 + i * 16 + (sel & 1) * 8) * 2;
                ldsm_x4t(a, aaddr);
                #pragma unroll
                for (int j = 0; j < 4; j++)
                    mma16816(acc[i][j], a, bb[2 * j], bb[2 * j + 1]);
            }
        }
        __syncthreads();
    }

    // epilogue: d~ = ||e||^2 - 2 s0, store bf16
    const int g = lane >> 2, tg = lane & 3;
    float cbn[8];
    #pragma unroll
    for (int j = 0; j < 4; j++) {
        cbn[2 * j]     = __ldg(&g_cbnorm[n0 + wn * 32 + j * 8 + tg * 2]);
        cbn[2 * j + 1] = __ldg(&g_cbnorm[n0 + wn * 32 + j * 8 + tg * 2 + 1]);
    }
    #pragma unroll
    for (int i = 0; i < 4; i++) {
        #pragma unroll
        for (int h = 0; h < 2; h++) {
            int row = m0 + wm * 64 + i * 16 + h * 8 + g;
            #pragma unroll
            for (int j = 0; j < 4; j++) {
                float d0 = cbn[2 * j]     - 2.0f * acc[i][j][h * 2];
                float d1 = cbn[2 * j + 1] - 2.0f * acc[i][j][h * 2 + 1];
                int col = n0 + wn * 32 + j * 8 + tg * 2;
                __nv_bfloat162 v = __halves2bfloat162(__float2bfloat16(d0), __float2bfloat16(d1));
                *(uint32_t*)(g_dmat + (size_t)row * NUM_E + col) = *(uint32_t*)&v;
            }
        }
    }
}

// ---------- pass 2: scan + exact refine + fused outputs (warp per row, 8 rows/block) ----------
__global__ __launch_bounds__(256) void refine_kernel(const float* __restrict__ z,
                                                     const float* __restrict__ cb,
                                                     float* __restrict__ oh,
                                                     float* __restrict__ oq) {
    __shared__ float zrow[8][256];
    __shared__ int sidx[8];
    const int bid = blockIdx.x, tid = threadIdx.x;
    const int w = tid >> 5, lane = tid & 31;
    const int r0 = bid * 8, b = r0 >> 10, hw0 = r0 & 1023;
    for (int e = tid; e < 2048; e += 256) {
        int rr = e & 7, c = e >> 3;
        zrow[rr][c] = z[(size_t)b * 262144 + (size_t)c * 1024 + hw0 + rr];
    }
    __syncthreads();
    const int row = r0 + w;

    float zn2 = 0.f;
    #pragma unroll
    for (int i = 0; i < 8; i++) { float v = zrow[w][lane + 32 * i]; zn2 += v * v; }
    #pragma unroll
    for (int o = 16; o; o >>= 1) zn2 += __shfl_xor_sync(0xffffffffu, zn2, o);

    // vectorized dmat scan: 4 x uint4 (8 bf16 each); dv[iq*8+j] -> col (iq*32+lane)*8+j
    const uint4* d4 = (const uint4*)(g_dmat + (size_t)row * NUM_E) + lane;
    uint4 qv[4];
    #pragma unroll
    for (int i = 0; i < 4; i++) qv[i] = d4[i * 32];
    float dv[32];
    float dmin = 3.4e38f;
    #pragma unroll
    for (int i = 0; i < 4; i++) {
        const uint32_t* pp = (const uint32_t*)&qv[i];
        #pragma unroll
        for (int hj = 0; hj < 4; hj++) {
            __nv_bfloat162 h = *(const __nv_bfloat162*)&pp[hj];
            float lo = __bfloat162float(__low2bfloat16(h));
            float hi = __bfloat162float(__high2bfloat16(h));
            dv[i * 8 + hj * 2]     = lo;
            dv[i * 8 + hj * 2 + 1] = hi;
            dmin = fminf(dmin, fminf(lo, hi));
        }
    }
    #pragma unroll
    for (int o = 16; o; o >>= 1) dmin = fminf(dmin, __shfl_xor_sync(0xffffffffu, dmin, o));

    float wmax = sqrtf(__uint_as_float(g_wmaxbits));      // max ||e||
    float T = dmin + 0.025f * sqrtf(zn2) * wmax + 8.0f;   // >3x proven bound

    // build per-lane candidate mask (no syncs), then ONE ballot
    unsigned cmask = 0;
    #pragma unroll
    for (int i = 0; i < 32; i++)
        if (dv[i] <= T) cmask |= (1u << i);

    unsigned long long best = ~0ull;
    unsigned active = __ballot_sync(0xffffffffu, cmask != 0);
    while (active) {
        int src = __ffs(active) - 1; active &= active - 1;
        unsigned bm = __shfl_sync(0xffffffffu, cmask, src);
        while (bm) {
            int i = __ffs(bm) - 1; bm &= bm - 1;
            int kc = ((i >> 3) * 32 + src) * 8 + (i & 7);
            const float* erow = cb + (size_t)kc * EDIM;
            float s = 0.f;
            #pragma unroll
            for (int jj = 0; jj < 8; jj++)
                s += zrow[w][lane + 32 * jj] * __ldg(&erow[lane + 32 * jj]);
            #pragma unroll
            for (int o = 16; o; o >>= 1) s += __shfl_xor_sync(0xffffffffu, s, o);
            float dist = __ldg(&g_cbnorm[kc]) - 2.0f * s;
            unsigned long long key = ((unsigned long long)ordf(dist) << 32) | (unsigned)kc;
            if (key < best) best = key;   // s warp-uniform -> best warp-uniform
        }
    }
    if (lane == 0) sidx[w] = (int)(best & 0xFFFFFFFFu);
    __syncthreads();

    // ---- fused outputs ----
    int idx[8];
    #pragma unroll
    for (int r = 0; r < 8; r++) idx[r] = sidx[r];

    // one-hot: 8 rows x 1024, float4 per thread per row
    #pragma unroll
    for (int r = 0; r < 8; r++) {
        int id = idx[r];
        float4 v = {0.f, 0.f, 0.f, 0.f};
        if ((id >> 2) == tid) {
            if ((id & 3) == 0) v.x = 1.f;
            else if ((id & 3) == 1) v.y = 1.f;
            else if ((id & 3) == 2) v.z = 1.f;
            else v.w = 1.f;
        }
        *(float4*)&oh[(size_t)(r0 + r) * NUM_E + tid * 4] = v;
    }

    // quant: thread t = channel c; vals[r] = cb[idx[r]*256 + c]; contiguous 8-float store
    float vals[8];
    #pragma unroll
    for (int r = 0; r < 8; r++)
        vals[r] = __ldg(&cb[(size_t)idx[r] * EDIM + tid]);
    float* qbase = oq + (size_t)b * 262144 + (size_t)tid * 1024 + hw0;
    *(float4*)qbase       = *(float4*)&vals[0];
    *(float4*)(qbase + 4) = *(float4*)&vals[4];
}

extern "C" void kernel_launch(void* const* d_in, const int* in_sizes, int n_in,
                              void* d_out, int out_size) {
    const float* z  = (const float*)d_in[0];
    const float* cb = (const float*)d_in[1];
    float* out_onehot = (float*)d_out;
    float* out_q      = (float*)d_out + (size_t)NROWS * NUM_E;

    cudaFuncSetAttribute(screen_kernel, cudaFuncAttributeMaxDynamicSharedMemorySize, SMEM_TOTAL);

    prep_kernel<<<3072, 256>>>(cb, z);
    screen_kernel<<<2048, 256, SMEM_TOTAL>>>();
    refine_kernel<<<NROWS / 8, 256>>>(z, cb, out_onehot, out_q);
}